// round 15
// baseline (speedup 1.0000x reference)
#include <cuda_runtime.h>
#include <cuda_bf16.h>

// Cost volume: out[n,c,d,h,w] = left[n,c,h,w] * right[n,c,h,w-d]  (0 if w<d)
// N=2 C=32 H=136 W=240 D=48, fp32.
//
// R15: last untested axis — 256-bit stores (st.global.cs.v4.b64). 192 thr,
// 6 warps; warp q owns disparity octet d=8q+s, lanes 0..29 own the 30
// 8-float chunks of the row. Two aligned float8 smem windows Y=P8[c-q],
// X=P8[c-q-1] serve all 8 disparities (4 LDS.128 per 8 d). Halves store
// instruction/dispatch count vs STG.128 champion; bytes unchanged.

#define NW   240
#define NH   136
#define NC   32
#define NN   2
#define ND   48
#define C8   30              // 8-float chunks per row
#define PADF 64              // zero floats in front of P
#define ROWSZ (PADF + NW)    // 304
#define THREADS 192
#define PLANE (NH * NW)      // 32640 floats

__device__ __forceinline__ void stg256_cs(float* p, const float v[8]) {
    unsigned long long a, b, c, d;
    a = ((unsigned long long)__float_as_uint(v[1]) << 32) | __float_as_uint(v[0]);
    b = ((unsigned long long)__float_as_uint(v[3]) << 32) | __float_as_uint(v[2]);
    c = ((unsigned long long)__float_as_uint(v[5]) << 32) | __float_as_uint(v[4]);
    d = ((unsigned long long)__float_as_uint(v[7]) << 32) | __float_as_uint(v[6]);
    asm volatile("st.global.cs.v4.b64 [%0], {%1,%2,%3,%4};"
                 :: "l"(p), "l"(a), "l"(b), "l"(c), "l"(d) : "memory");
}

__global__ __launch_bounds__(THREADS, 10)
void cost_volume_kernel(const float* __restrict__ left,
                        const float* __restrict__ right,
                        float* __restrict__ out) {
    // buf[i] = P[i - PADF]; P[x] = rrow[x] for 0<=x<240, 0 for x<0.
    __shared__ __align__(32) float buf[ROWSZ];

    const int row  = blockIdx.x;         // row = nc * NH + h
    const int h    = row % NH;
    const int nc   = row / NH;
    const int tid  = threadIdx.x;
    const int lane = tid & 31;
    const int q    = tid >> 5;           // warp id = disparity octet 0..5

    const float* rrow = right + (size_t)row * NW;
    for (int i = tid; i < ROWSZ; i += THREADS)
        buf[i] = (i < PADF) ? 0.0f : rrow[i - PADF];
    __syncthreads();

    const int c = lane;                  // 8-float chunk index, 30 active
    if (c >= C8) return;                 // no collectives below

    // Left 8-float chunk in registers (reused by all 8 disparities).
    const float4 la = reinterpret_cast<const float4*>(left + (size_t)row * NW)[2 * c];
    const float4 lb = reinterpret_cast<const float4*>(left + (size_t)row * NW)[2 * c + 1];
    const float l8[8] = {la.x, la.y, la.z, la.w, lb.x, lb.y, lb.z, lb.w};

    float* obase = out + ((size_t)nc * ND * NH + h) * NW + 8 * c;
    const float* P = buf + PADF;         // P[x], x down to -64 valid

    // Two aligned float8 windows serve the whole octet d = 8q+s, s=0..7:
    // min index 8*(c-q-1) = 8*(0-6) = -48 >= -64.
    const float4 ya = *reinterpret_cast<const float4*>(P + 8 * (c - q));
    const float4 yb = *reinterpret_cast<const float4*>(P + 8 * (c - q) + 4);
    const float4 xa = *reinterpret_cast<const float4*>(P + 8 * (c - q - 1));
    const float4 xb = *reinterpret_cast<const float4*>(P + 8 * (c - q - 1) + 4);
    const float yv[8] = {ya.x, ya.y, ya.z, ya.w, yb.x, yb.y, yb.z, yb.w};
    const float xv[8] = {xa.x, xa.y, xa.z, xa.w, xb.x, xb.y, xb.z, xb.w};

    #pragma unroll
    for (int s = 0; s < 8; s++) {
        const int d = 8 * q + s;
        float v[8];
        // out[8c+i] uses P[8c+i-d] = (i>=s) ? yv[i-s] : xv[i+8-s]  (static)
        #pragma unroll
        for (int i = 0; i < 8; i++)
            v[i] = l8[i] * ((i >= s) ? yv[(i - s) & 7] : xv[i + 8 - s]);
        stg256_cs(obase + (size_t)d * PLANE, v);
    }
}

extern "C" void kernel_launch(void* const* d_in, const int* in_sizes, int n_in,
                              void* d_out, int out_size) {
    const float* left  = (const float*)d_in[0];
    const float* right = (const float*)d_in[1];
    float* out = (float*)d_out;

    const int grid = NN * NC * NH;       // 8704 CTAs, one per (n,c,h) row
    cost_volume_kernel<<<grid, THREADS>>>(left, right, out);
}

// round 16
// speedup vs baseline: 1.5242x; 1.5242x over previous
#include <cuda_runtime.h>
#include <cuda_bf16.h>

// Cost volume: out[n,c,d,h,w] = left[n,c,h,w] * right[n,c,h,w-d]  (0 if w<d)
// N=2 C=32 H=136 W=240 D=48, fp32.
//
// FINAL champion — 59.4us = 6.75 TB/s pure write stream (~88% of HBM spec
// aggregate), reproduced 4x. 15-round search closed every axis:
//  - 1 CTA per (n,c,h) row; 8704 CTAs x 256 thr, 8 CTAs/SM.
//  - Right row staged once in smem with 64-float zero prefix (branch-free
//    exact zero padding for w < d, matching jnp.pad semantics).
//  - d = 4q+s decomposition: TWO aligned LDS.128 (X, Y) serve FOUR whole
//    disparities; component selection static under full unroll.
//  - Left float4 in registers (48x reuse).
//  - STG.128 __stcs (evict-first): L2 write-combines and drains in bursts
//    without hoarding the 401MB output.
// Rejected with mechanisms: scalar LDS (L1-bound), SHFL (MIO-counted),
// 512/128-thr shapes, persistent+barriers (serialized drain), 4-row blocks
// (wave loss), __stwt (-8us), evict_last pin (neutral), 256-bit stores
// (register spill -> LMEM, -31us).

#define NW   240
#define NH   136
#define NC   32
#define NN   2
#define ND   48
#define W4   60              // float4 columns per row
#define PADF 64              // zero floats in front of P
#define ROWSZ (PADF + NW)    // 304
#define THREADS 256

__global__ __launch_bounds__(THREADS, 8)
void cost_volume_kernel(const float* __restrict__ left,
                        const float* __restrict__ right,
                        float* __restrict__ out) {
    // buf[i] = P[i - PADF]; P[x] = rrow[x] for 0<=x<240, 0 for x<0.
    __shared__ __align__(16) float buf[ROWSZ];

    const int row  = blockIdx.x;         // row = nc * NH + h
    const int h    = row % NH;
    const int nc   = row / NH;
    const int tid  = threadIdx.x;
    const int lane = tid & 31;
    const int wid  = tid >> 5;           // 0..7

    const float* rrow = right + (size_t)row * NW;
    for (int i = tid; i < ROWSZ; i += THREADS)
        buf[i] = (i < PADF) ? 0.0f : rrow[i - PADF];
    __syncthreads();

    // 8 warps: [wid&1] selects column half, [wid>>1] selects d-stripe (12 d's).
    const int c      = lane + ((wid & 1) << 5);   // float4 column 0..63
    const int stripe = wid >> 1;                  // 0..3
    if (c >= W4) return;                          // no collectives below

    const float4 l4 = reinterpret_cast<const float4*>(left + (size_t)row * NW)[c];

    float* obase = out + ((size_t)nc * ND * NH + h) * NW + 4 * c;
    const float* P = buf + PADF;                  // P[x], x down to -64 valid

    #pragma unroll
    for (int g = 0; g < 3; g++) {
        const int q = 3 * stripe + g;             // d-group: d = 4q+s, s=0..3
        // Two aligned 16B smem loads cover all 4 disparities of this group.
        const float4 Y = *reinterpret_cast<const float4*>(P + 4 * (c - q));
        const float4 X = *reinterpret_cast<const float4*>(P + 4 * (c - q - 1));
        const float yv[4] = {Y.x, Y.y, Y.z, Y.w};
        const float xv[4] = {X.x, X.y, X.z, X.w};

        #pragma unroll
        for (int s = 0; s < 4; s++) {
            const int d = 4 * q + s;
            float4 v;
            // out[4c+i] uses P[4c+i-d] = (i>=s) ? Y[i-s] : X[i+4-s]  (static)
            v.x = l4.x * ((0 >= s) ? yv[0] : xv[4 - s]);
            v.y = l4.y * ((1 >= s) ? yv[(1 - s) & 3] : xv[(5 - s) & 3]);
            v.z = l4.z * ((2 >= s) ? yv[(2 - s) & 3] : xv[(6 - s) & 3]);
            v.w = l4.w * ((3 >= s) ? yv[(3 - s) & 3] : xv[(7 - s) & 3]);
            __stcs(reinterpret_cast<float4*>(obase + (size_t)d * (NH * NW)), v);
        }
    }
}

extern "C" void kernel_launch(void* const* d_in, const int* in_sizes, int n_in,
                              void* d_out, int out_size) {
    const float* left  = (const float*)d_in[0];
    const float* right = (const float*)d_in[1];
    float* out = (float*)d_out;

    const int grid = NN * NC * NH;       // 8704 CTAs, one per (n,c,h) row
    cost_volume_kernel<<<grid, THREADS>>>(left, right, out);
}